// round 1
// baseline (speedup 1.0000x reference)
#include <cuda_runtime.h>
#include <math.h>

#define Bdim 64
#define Idim 2048
#define Hdim 2048
#define Tdim 128

// Scratch (static device globals: allocation-free, graph-capturable)
__device__ float g_weff[Idim * Hdim];                       // 16 MB
__device__ float g_spkT[(size_t)Tdim * Bdim * Idim];        // 64 MB  [T][B][I]
__device__ float g_weighted[(size_t)Tdim * Bdim * Hdim];    // 64 MB  [T][B][H]

// ---------------------------------------------------------------------------
// w_eff = weight * synaptic_strength
// ---------------------------------------------------------------------------
__global__ void weff_kernel(const float4* __restrict__ w, const float4* __restrict__ s) {
    int i = blockIdx.x * 256 + threadIdx.x;
    if (i < (Idim * Hdim) / 4) {
        float4 a = w[i], b = s[i];
        float4 r;
        r.x = a.x * b.x; r.y = a.y * b.y; r.z = a.z * b.z; r.w = a.w * b.w;
        reinterpret_cast<float4*>(g_weff)[i] = r;
    }
}

// ---------------------------------------------------------------------------
// Transpose spikes [B][I][T] -> [T][B][I]
// ---------------------------------------------------------------------------
__global__ void transpose_kernel(const float* __restrict__ in) {
    __shared__ float tile[32][33];
    int t0 = blockIdx.x * 32;
    int i0 = blockIdx.y * 32;
    int b  = blockIdx.z;
    int tx = threadIdx.x, ty = threadIdx.y;
#pragma unroll
    for (int j = 0; j < 32; j += 8)
        tile[ty + j][tx] = in[((size_t)b * Idim + i0 + ty + j) * Tdim + t0 + tx];
    __syncthreads();
#pragma unroll
    for (int j = 0; j < 32; j += 8)
        g_spkT[((size_t)(t0 + ty + j) * Bdim + b) * Idim + i0 + tx] = tile[tx][ty + j];
}

// ---------------------------------------------------------------------------
// Batched GEMM: weighted[t] (64 x 2048) = spkT[t] (64 x 2048) @ w_eff (2048 x 2048)
// fp32 SIMT, BM=64 BN=128 BK=16, 128 threads, 8x8 per thread.
// ---------------------------------------------------------------------------
__global__ __launch_bounds__(128, 2) void gemm_kernel() {
    __shared__ float As[16][64];    // transposed: As[k][m]
    __shared__ float Bs[16][128];

    int tid = threadIdx.x;
    int t   = blockIdx.y;
    int n0  = blockIdx.x * 128;
    const float* A = g_spkT + (size_t)t * (Bdim * Idim);

    float acc[8][8];
#pragma unroll
    for (int i = 0; i < 8; i++)
#pragma unroll
        for (int j = 0; j < 8; j++) acc[i][j] = 0.0f;

    int row0 = (tid >> 4) * 8;   // m base (0..56)
    int col0 = (tid & 15) * 8;   // n base (0..120)

    for (int k0 = 0; k0 < Idim; k0 += 16) {
        // Load A tile 64x16 (2 float4 per thread), store transposed
#pragma unroll
        for (int l = 0; l < 2; l++) {
            int e = tid + l * 128;       // float4 index in [0,256)
            int r = e >> 2;              // m row 0..63
            int c = (e & 3) * 4;         // k col {0,4,8,12}
            float4 va = *reinterpret_cast<const float4*>(A + (size_t)r * Idim + k0 + c);
            As[c + 0][r] = va.x; As[c + 1][r] = va.y;
            As[c + 2][r] = va.z; As[c + 3][r] = va.w;
        }
        // Load B tile 16x128 (4 float4 per thread)
#pragma unroll
        for (int l = 0; l < 4; l++) {
            int e = tid + l * 128;       // float4 index in [0,512)
            int r = e >> 5;              // k row 0..15
            int c = (e & 31) * 4;        // n col
            *reinterpret_cast<float4*>(&Bs[r][c]) =
                *reinterpret_cast<const float4*>(g_weff + (size_t)(k0 + r) * Hdim + n0 + c);
        }
        __syncthreads();

#pragma unroll
        for (int kk = 0; kk < 16; ++kk) {
            float am[8], bn[8];
            *reinterpret_cast<float4*>(am)     = *reinterpret_cast<float4*>(&As[kk][row0]);
            *reinterpret_cast<float4*>(am + 4) = *reinterpret_cast<float4*>(&As[kk][row0 + 4]);
            *reinterpret_cast<float4*>(bn)     = *reinterpret_cast<float4*>(&Bs[kk][col0]);
            *reinterpret_cast<float4*>(bn + 4) = *reinterpret_cast<float4*>(&Bs[kk][col0 + 4]);
#pragma unroll
            for (int i = 0; i < 8; i++)
#pragma unroll
                for (int j = 0; j < 8; j++)
                    acc[i][j] = fmaf(am[i], bn[j], acc[i][j]);
        }
        __syncthreads();
    }

    float* D = g_weighted + ((size_t)t * Bdim + row0) * Hdim + n0 + col0;
#pragma unroll
    for (int i = 0; i < 8; i++) {
        *reinterpret_cast<float4*>(D + (size_t)i * Hdim)     = *reinterpret_cast<float4*>(&acc[i][0]);
        *reinterpret_cast<float4*>(D + (size_t)i * Hdim + 4) = *reinterpret_cast<float4*>(&acc[i][4]);
    }
}

// ---------------------------------------------------------------------------
// Sequential LIF scan with homeostatic threshold.
// Block = 8 h-columns x 64 batches = 512 threads; loops t=0..127 internally.
// Threshold couples batches only within an h-column, so blocks are independent.
// ---------------------------------------------------------------------------
__global__ __launch_bounds__(512, 2) void scan_kernel(
    const float* __restrict__ threshold,
    const float* __restrict__ p_tau_mem, const float* __restrict__ p_tau_syn,
    const float* __restrict__ p_target,  const float* __restrict__ p_lr,
    float* __restrict__ out)
{
    __shared__ float s_thr[8];
    __shared__ float s_fre[8];
    __shared__ float s_part[16][8];

    int tid     = threadIdx.x;
    int h_local = tid & 7;
    int b       = tid >> 3;
    int hblk    = blockIdx.x * 8;

    float tau_m = *p_tau_mem, tau_s = *p_tau_syn;
    // match jnp.exp(-DT/tau) with DT weak-typed to f32: f32 division, then exp
    float a_mem = (float)exp(-(double)(0.001f / tau_m));
    float a_syn = (float)exp(-(double)(0.001f / tau_s));
    float target = *p_target, lr = *p_lr;

    if (tid < 8) { s_thr[tid] = threshold[hblk + tid]; s_fre[tid] = 0.0f; }
    __syncthreads();

    float isyn = 0.0f, v = 0.0f;
    unsigned sb[4] = {0u, 0u, 0u, 0u};
    const float* wptr = g_weighted + (size_t)b * Hdim + hblk + h_local;

    for (int t = 0; t < Tdim; ++t) {
        float w = wptr[(size_t)t * Bdim * Hdim];
        isyn = fmaf(a_syn, isyn, w);
        v    = fmaf(a_mem, v, isyn);
        float thr = s_thr[h_local];
        float sp  = (v >= thr) ? 1.0f : 0.0f;
        v -= sp * thr;
        if (sp != 0.0f) sb[t >> 5] |= (1u << (t & 31));

        // Reduce spikes over b (64 values per h): intra-warp (4 b's), then smem
        float r = sp;
        r += __shfl_down_sync(0xffffffffu, r, 16);
        r += __shfl_down_sync(0xffffffffu, r, 8);
        if ((tid & 31) < 8) s_part[tid >> 5][tid & 7] = r;
        __syncthreads();
        if (tid < 8) {
            float s = 0.0f;
#pragma unroll
            for (int wi = 0; wi < 16; ++wi) s += s_part[wi][tid];
            float rate = s * (1.0f / 64.0f);           // exact: integer / 64
            float fre  = 0.99f * s_fre[tid] + 0.01f * rate;
            s_fre[tid] = fre;
            s_thr[tid] = s_thr[tid] + lr * (fre - target);
        }
        __syncthreads();
    }

    // Write out[b][h][t]: each thread owns a contiguous 128-float run
    float* p = out + ((size_t)b * Hdim + hblk + h_local) * Tdim;
#pragma unroll
    for (int wi = 0; wi < 4; ++wi) {
#pragma unroll
        for (int j = 0; j < 32; j += 4) {
            float4 o;
            o.x = (float)((sb[wi] >> (j + 0)) & 1u);
            o.y = (float)((sb[wi] >> (j + 1)) & 1u);
            o.z = (float)((sb[wi] >> (j + 2)) & 1u);
            o.w = (float)((sb[wi] >> (j + 3)) & 1u);
            *reinterpret_cast<float4*>(p + wi * 32 + j) = o;
        }
    }
}

// ---------------------------------------------------------------------------
extern "C" void kernel_launch(void* const* d_in, const int* in_sizes, int n_in,
                              void* d_out, int out_size) {
    const float* spikes    = (const float*)d_in[0];
    const float* weight    = (const float*)d_in[1];
    const float* strength  = (const float*)d_in[2];
    const float* threshold = (const float*)d_in[3];
    const float* tau_mem   = (const float*)d_in[4];
    const float* tau_syn   = (const float*)d_in[5];
    const float* target    = (const float*)d_in[6];
    const float* lr        = (const float*)d_in[7];
    float* out = (float*)d_out;

    weff_kernel<<<(Idim * Hdim / 4 + 255) / 256, 256>>>(
        (const float4*)weight, (const float4*)strength);

    dim3 tg(Tdim / 32, Idim / 32, Bdim);
    transpose_kernel<<<tg, dim3(32, 8)>>>(spikes);

    gemm_kernel<<<dim3(Hdim / 128, Tdim), 128>>>();

    scan_kernel<<<Hdim / 8, 512>>>(threshold, tau_mem, tau_syn, target, lr, out);
}

// round 4
// speedup vs baseline: 2.5516x; 2.5516x over previous
#include <cuda_runtime.h>
#include <cuda_fp16.h>
#include <cstdint>
#include <math.h>

#define Bdim 64
#define Idim 2048
#define Hdim 2048
#define Tdim 128
#define Mtot (Tdim * Bdim)          // 8192 rows (t,b)

// ---------------- scratch (device globals; allocation-free) ----------------
__device__ __half g_Ah[(size_t)Mtot * Idim];        // 32 MB  [t*B+b][i] fp16 spikes
__device__ __half g_w0[(size_t)Hdim * Idim];        // 8 MB   hi plane   [h][i]
__device__ __half g_w1[(size_t)Hdim * Idim];        // 8 MB   res*2^11   [h][i]
__device__ float  g_weighted[(size_t)Mtot * Hdim];  // 64 MB  [t*B+b][h]

// ---------------------------------------------------------------------------
// Split + transpose: w_eff = W*S [I][H] fp32 -> 2 fp16 planes [H][I]
//   hi = rn16(v); res = (v - hi) exact in fp32; plane1 = rn16(res * 2^11)
// ---------------------------------------------------------------------------
__global__ void split_kernel(const float* __restrict__ w, const float* __restrict__ s) {
    __shared__ float tile[32][33];
    int i0 = blockIdx.x * 32, h0 = blockIdx.y * 32;
    int tx = threadIdx.x, ty = threadIdx.y;
#pragma unroll
    for (int j = 0; j < 32; j += 8) {
        size_t idx = (size_t)(i0 + ty + j) * Hdim + h0 + tx;
        tile[ty + j][tx] = w[idx] * s[idx];
    }
    __syncthreads();
#pragma unroll
    for (int j = 0; j < 32; j += 8) {
        float v = tile[tx][ty + j];                 // [i=tx][h=ty+j]
        __half hi = __float2half_rn(v);
        float r = v - __half2float(hi);             // exact
        __half lo = __float2half_rn(r * 2048.0f);
        size_t o = (size_t)(h0 + ty + j) * Idim + i0 + tx;
        g_w0[o] = hi;
        g_w1[o] = lo;
    }
}

// ---------------------------------------------------------------------------
// Spikes [B][I][T] fp32 -> A fp16 [(t*B+b)][i]  (0/1 exact in fp16)
// ---------------------------------------------------------------------------
__global__ void spike_kernel(const float* __restrict__ in) {
    __shared__ float tile[32][33];
    int t0 = blockIdx.x * 32, i0 = blockIdx.y * 32, b = blockIdx.z;
    int tx = threadIdx.x, ty = threadIdx.y;
#pragma unroll
    for (int j = 0; j < 32; j += 8)
        tile[ty + j][tx] = in[((size_t)b * Idim + i0 + ty + j) * Tdim + t0 + tx];
    __syncthreads();
#pragma unroll
    for (int j = 0; j < 32; j += 8)
        g_Ah[((size_t)(t0 + ty + j) * Bdim + b) * Idim + i0 + tx] =
            __float2half_rn(tile[tx][ty + j]);
}

// ---------------------------------------------------------------------------
// mma.sync GEMM: C[8192 x 2048] = A @ W0^T + 2^-11 * (A @ W1^T), fp32 acc
// CTA 128x128, BK=32, 8 warps (4m x 2n), warp tile 32x64, m16n8k16 HMMA.
// smem rows padded to 40 halves (80 B): 5 coprime 8 -> conflict-free LDS.
// ---------------------------------------------------------------------------
#define BM 128
#define BN 128
#define BK 32
#define ASTR 40                    // halves per smem row (80 B)

__device__ __forceinline__ void tile_load(__half* dst, const __half* src, int kt, int tid) {
    int k0 = kt * BK;
#pragma unroll
    for (int i = 0; i < 2; i++) {
        int ch = tid + i * 256;            // 0..511 chunks of 16B
        int r = ch >> 2, c = ch & 3;
        uint32_t d = (uint32_t)__cvta_generic_to_shared(dst + r * ASTR + c * 8);
        asm volatile("cp.async.cg.shared.global [%0], [%1], 16;"
                     :: "r"(d), "l"(src + (size_t)r * Idim + k0 + c * 8));
    }
}

__global__ __launch_bounds__(256) void gemm_mma_kernel() {
    __shared__ __half sA[2][BM * ASTR];    // 2 x 10240 B
    __shared__ __half sB[2][BN * ASTR];

    int tid  = threadIdx.x;
    int lane = tid & 31;
    int wid  = tid >> 5;
    int wm = (wid >> 1) * 32;              // warp m offset (0,32,64,96)
    int wn = (wid & 1) * 64;               // warp n offset (0,64)
    int lr = lane >> 2;                    // 0..7
    int lc = lane & 3;                     // 0..3
    int m0 = blockIdx.y * BM;
    int n0 = blockIdx.x * BN;

    const __half* Asrc = g_Ah + (size_t)m0 * Idim;

    float acc[2][8][4];
#pragma unroll
    for (int mt = 0; mt < 2; mt++)
#pragma unroll
        for (int nt = 0; nt < 8; nt++)
#pragma unroll
            for (int q = 0; q < 4; q++) acc[mt][nt][q] = 0.0f;

    const int NKT = Idim / BK;             // 64

#pragma unroll 1
    for (int pass = 0; pass < 2; pass++) {
        const __half* Bsrc = (pass == 0 ? g_w1 : g_w0) + (size_t)n0 * Idim;

        tile_load(sA[0], Asrc, 0, tid);
        tile_load(sB[0], Bsrc, 0, tid);
        asm volatile("cp.async.commit_group;" ::: "memory");
        tile_load(sA[1], Asrc, 1, tid);
        tile_load(sB[1], Bsrc, 1, tid);
        asm volatile("cp.async.commit_group;" ::: "memory");

#pragma unroll 1
        for (int kt = 0; kt < NKT; kt++) {
            int buf = kt & 1;
            if (kt < NKT - 1) asm volatile("cp.async.wait_group 1;" ::: "memory");
            else              asm volatile("cp.async.wait_group 0;" ::: "memory");
            __syncthreads();

            const __half* A = sA[buf];
            const __half* B = sB[buf];
#pragma unroll
            for (int ks = 0; ks < 2; ks++) {
                int kb = ks * 16 + lc * 2;
                uint32_t a[2][4];
#pragma unroll
                for (int mt = 0; mt < 2; mt++) {
                    const __half* ap = A + (wm + mt * 16 + lr) * ASTR + kb;
                    a[mt][0] = *(const uint32_t*)ap;
                    a[mt][1] = *(const uint32_t*)(ap + 8 * ASTR);
                    a[mt][2] = *(const uint32_t*)(ap + 8);
                    a[mt][3] = *(const uint32_t*)(ap + 8 * ASTR + 8);
                }
#pragma unroll
                for (int nt = 0; nt < 8; nt++) {
                    const __half* bp = B + (wn + nt * 8 + lr) * ASTR + kb;
                    uint32_t b0 = *(const uint32_t*)bp;
                    uint32_t b1 = *(const uint32_t*)(bp + 8);
#pragma unroll
                    for (int mt = 0; mt < 2; mt++) {
                        float* c = acc[mt][nt];
                        asm volatile(
                            "mma.sync.aligned.m16n8k16.row.col.f32.f16.f16.f32 "
                            "{%0,%1,%2,%3}, {%4,%5,%6,%7}, {%8,%9}, {%0,%1,%2,%3};"
                            : "+f"(c[0]), "+f"(c[1]), "+f"(c[2]), "+f"(c[3])
                            : "r"(a[mt][0]), "r"(a[mt][1]), "r"(a[mt][2]), "r"(a[mt][3]),
                              "r"(b0), "r"(b1));
                    }
                }
            }
            __syncthreads();
            if (kt < NKT - 2) {
                tile_load(sA[buf], Asrc, kt + 2, tid);
                tile_load(sB[buf], Bsrc, kt + 2, tid);
                asm volatile("cp.async.commit_group;" ::: "memory");
            }
        }

        if (pass == 0) {                    // acc = 2^-11 * C_res, exact scale
#pragma unroll
            for (int mt = 0; mt < 2; mt++)
#pragma unroll
                for (int nt = 0; nt < 8; nt++)
#pragma unroll
                    for (int q = 0; q < 4; q++) acc[mt][nt][q] *= 4.8828125e-4f;
            __syncthreads();
        }
    }

    // Epilogue: acc -> g_weighted
#pragma unroll
    for (int mt = 0; mt < 2; mt++) {
        int row = m0 + wm + mt * 16 + lr;
#pragma unroll
        for (int nt = 0; nt < 8; nt++) {
            int col = n0 + wn + nt * 8 + lc * 2;
            float2 v0 = make_float2(acc[mt][nt][0], acc[mt][nt][1]);
            float2 v1 = make_float2(acc[mt][nt][2], acc[mt][nt][3]);
            *reinterpret_cast<float2*>(&g_weighted[(size_t)row * Hdim + col])       = v0;
            *reinterpret_cast<float2*>(&g_weighted[(size_t)(row + 8) * Hdim + col]) = v1;
        }
    }
}

// ---------------------------------------------------------------------------
// Sequential LIF scan with homeostatic threshold (unchanged from R1).
// ---------------------------------------------------------------------------
__global__ __launch_bounds__(512, 2) void scan_kernel(
    const float* __restrict__ threshold,
    const float* __restrict__ p_tau_mem, const float* __restrict__ p_tau_syn,
    const float* __restrict__ p_target,  const float* __restrict__ p_lr,
    float* __restrict__ out)
{
    __shared__ float s_thr[8];
    __shared__ float s_fre[8];
    __shared__ float s_part[16][8];

    int tid     = threadIdx.x;
    int h_local = tid & 7;
    int b       = tid >> 3;
    int hblk    = blockIdx.x * 8;

    float tau_m = *p_tau_mem, tau_s = *p_tau_syn;
    float a_mem = (float)exp(-(double)(0.001f / tau_m));
    float a_syn = (float)exp(-(double)(0.001f / tau_s));
    float target = *p_target, lr = *p_lr;

    if (tid < 8) { s_thr[tid] = threshold[hblk + tid]; s_fre[tid] = 0.0f; }
    __syncthreads();

    float isyn = 0.0f, v = 0.0f;
    unsigned sb[4] = {0u, 0u, 0u, 0u};
    const float* wptr = g_weighted + (size_t)b * Hdim + hblk + h_local;

    for (int t = 0; t < Tdim; ++t) {
        float w = wptr[(size_t)t * Bdim * Hdim];
        isyn = fmaf(a_syn, isyn, w);
        v    = fmaf(a_mem, v, isyn);
        float thr = s_thr[h_local];
        float sp  = (v >= thr) ? 1.0f : 0.0f;
        v -= sp * thr;
        if (sp != 0.0f) sb[t >> 5] |= (1u << (t & 31));

        float r = sp;
        r += __shfl_down_sync(0xffffffffu, r, 16);
        r += __shfl_down_sync(0xffffffffu, r, 8);
        if ((tid & 31) < 8) s_part[tid >> 5][tid & 7] = r;
        __syncthreads();
        if (tid < 8) {
            float s = 0.0f;
#pragma unroll
            for (int wi = 0; wi < 16; ++wi) s += s_part[wi][tid];
            float rate = s * (1.0f / 64.0f);
            float fre  = 0.99f * s_fre[tid] + 0.01f * rate;
            s_fre[tid] = fre;
            s_thr[tid] = s_thr[tid] + lr * (fre - target);
        }
        __syncthreads();
    }

    float* p = out + ((size_t)b * Hdim + hblk + h_local) * Tdim;
#pragma unroll
    for (int wi = 0; wi < 4; ++wi) {
#pragma unroll
        for (int j = 0; j < 32; j += 4) {
            float4 o;
            o.x = (float)((sb[wi] >> (j + 0)) & 1u);
            o.y = (float)((sb[wi] >> (j + 1)) & 1u);
            o.z = (float)((sb[wi] >> (j + 2)) & 1u);
            o.w = (float)((sb[wi] >> (j + 3)) & 1u);
            *reinterpret_cast<float4*>(p + wi * 32 + j) = o;
        }
    }
}

// ---------------------------------------------------------------------------
extern "C" void kernel_launch(void* const* d_in, const int* in_sizes, int n_in,
                              void* d_out, int out_size) {
    const float* spikes    = (const float*)d_in[0];
    const float* weight    = (const float*)d_in[1];
    const float* strength  = (const float*)d_in[2];
    const float* threshold = (const float*)d_in[3];
    const float* tau_mem   = (const float*)d_in[4];
    const float* tau_syn   = (const float*)d_in[5];
    const float* target    = (const float*)d_in[6];
    const float* lr        = (const float*)d_in[7];
    float* out = (float*)d_out;

    split_kernel<<<dim3(Idim / 32, Hdim / 32), dim3(32, 8)>>>(weight, strength);
    spike_kernel<<<dim3(Tdim / 32, Idim / 32, Bdim), dim3(32, 8)>>>(spikes);
    gemm_mma_kernel<<<dim3(Hdim / BN, Mtot / BM), 256>>>();
    scan_kernel<<<Hdim / 8, 512>>>(threshold, tau_mem, tau_syn, target, lr, out);
}

// round 5
// speedup vs baseline: 2.7564x; 1.0802x over previous
#include <cuda_runtime.h>
#include <cuda_fp16.h>
#include <cstdint>
#include <math.h>

#define Bdim 64
#define Idim 2048
#define Hdim 2048
#define Tdim 128
#define Mtot (Tdim * Bdim)          // 8192 rows (t,b)

// ---------------- scratch (device globals; allocation-free) ----------------
__device__ __half g_Ah[(size_t)Mtot * Idim];        // 32 MB  [t*B+b][i] fp16 spikes
__device__ __half g_w0[(size_t)Hdim * Idim];        // 8 MB   hi plane   [h][i]
__device__ __half g_w1[(size_t)Hdim * Idim];        // 8 MB   res*2^11   [h][i]
__device__ float  g_weighted[(size_t)Mtot * Hdim];  // 64 MB  [t*B+b][h]

// ---------------------------------------------------------------------------
// Split + transpose: w_eff = W*S [I][H] fp32 -> 2 fp16 planes [H][I]
// ---------------------------------------------------------------------------
__global__ void split_kernel(const float* __restrict__ w, const float* __restrict__ s) {
    __shared__ float tile[32][33];
    int i0 = blockIdx.x * 32, h0 = blockIdx.y * 32;
    int tx = threadIdx.x, ty = threadIdx.y;
#pragma unroll
    for (int j = 0; j < 32; j += 8) {
        size_t idx = (size_t)(i0 + ty + j) * Hdim + h0 + tx;
        tile[ty + j][tx] = w[idx] * s[idx];
    }
    __syncthreads();
#pragma unroll
    for (int j = 0; j < 32; j += 8) {
        float v = tile[tx][ty + j];                 // [i=tx][h=ty+j]
        __half hi = __float2half_rn(v);
        float r = v - __half2float(hi);             // exact (Fast2Sum)
        __half lo = __float2half_rn(r * 2048.0f);
        size_t o = (size_t)(h0 + ty + j) * Idim + i0 + tx;
        g_w0[o] = hi;
        g_w1[o] = lo;
    }
}

// ---------------------------------------------------------------------------
// Spikes [B][I][T] fp32 -> A fp16 [(t*B+b)][i]
// ---------------------------------------------------------------------------
__global__ void spike_kernel(const float* __restrict__ in) {
    __shared__ float tile[32][33];
    int t0 = blockIdx.x * 32, i0 = blockIdx.y * 32, b = blockIdx.z;
    int tx = threadIdx.x, ty = threadIdx.y;
#pragma unroll
    for (int j = 0; j < 32; j += 8)
        tile[ty + j][tx] = in[((size_t)b * Idim + i0 + ty + j) * Tdim + t0 + tx];
    __syncthreads();
#pragma unroll
    for (int j = 0; j < 32; j += 8)
        g_Ah[((size_t)(t0 + ty + j) * Bdim + b) * Idim + i0 + tx] =
            __float2half_rn(tile[tx][ty + j]);
}

// ---------------------------------------------------------------------------
// mma.sync GEMM: C = A @ W0^T + 2^-11 * (A @ W1^T), fp32 acc.
// CTA 128x256, BK=64, 512 threads (16 warps, warp tile 32x64), 3-stage
// cp.async pipeline, ldmatrix.x4 fragments, fused 64-kt loop (pass switch
// at kt=32 with exact 2^-11 acc scale).
// ---------------------------------------------------------------------------
#define BM 128
#define BN 256
#define BK 64
#define ASTR 72                          // halves per smem row (144 B)
#define A_STG_H (BM * ASTR)              // 9216 halves = 18432 B
#define B_STG_H (BN * ASTR)              // 18432 halves = 36864 B
#define STAGE_BYTES ((A_STG_H + B_STG_H) * 2)   // 55296 B
#define GEMM_SMEM (3 * STAGE_BYTES)             // 165888 B
#define NKT 64                            // 2 passes x 32 k-tiles

__device__ __forceinline__ void ldsm_x4(uint32_t* r, uint32_t addr) {
    asm volatile("ldmatrix.sync.aligned.m8n8.x4.shared.b16 {%0,%1,%2,%3}, [%4];"
                 : "=r"(r[0]), "=r"(r[1]), "=r"(r[2]), "=r"(r[3]) : "r"(addr));
}

__device__ __forceinline__ void stage_load(uint32_t sbase, int stage, int kt,
                                           int tid, int m0, int n0) {
    const __half* Asrc = g_Ah + (size_t)m0 * Idim;
    const __half* Bsrc = (kt < 32 ? g_w1 : g_w0) + (size_t)n0 * Idim;
    int k0 = (kt & 31) * BK;
    uint32_t sA = sbase + (uint32_t)stage * STAGE_BYTES;
    uint32_t sB = sA + A_STG_H * 2;
#pragma unroll
    for (int i = 0; i < 2; i++) {               // A: 128 rows x 8 chunks16B
        int ch = tid + i * 512;
        int r = ch >> 3, c = ch & 7;
        uint32_t d = sA + (uint32_t)(r * ASTR + c * 8) * 2;
        asm volatile("cp.async.cg.shared.global [%0], [%1], 16;"
                     :: "r"(d), "l"(Asrc + (size_t)r * Idim + k0 + c * 8));
    }
#pragma unroll
    for (int i = 0; i < 4; i++) {               // B: 256 rows x 8 chunks16B
        int ch = tid + i * 512;
        int r = ch >> 3, c = ch & 7;
        uint32_t d = sB + (uint32_t)(r * ASTR + c * 8) * 2;
        asm volatile("cp.async.cg.shared.global [%0], [%1], 16;"
                     :: "r"(d), "l"(Bsrc + (size_t)r * Idim + k0 + c * 8));
    }
}

__global__ __launch_bounds__(512, 1) void gemm_mma_kernel() {
    extern __shared__ char smem[];
    uint32_t sbase = (uint32_t)__cvta_generic_to_shared(smem);

    int tid  = threadIdx.x;
    int lane = tid & 31;
    int wid  = tid >> 5;
    int wm = (wid >> 2) * 32;            // 0,32,64,96
    int wn = (wid & 3) * 64;             // 0,64,128,192
    int lr = lane >> 2;                  // 0..7
    int lc = lane & 3;                   // 0..3
    int m0 = blockIdx.y * BM;
    int n0 = blockIdx.x * BN;

    // per-lane ldmatrix row/col selectors
    int a_row  = wm + (lane & 15);
    int a_csel = (lane >> 4) << 3;                    // 0 / 8
    int b_row  = ((lane >> 4) << 3) + (lane & 7);     // 0..15
    int b_csel = ((lane >> 3) & 1) << 3;              // 0 / 8

    float acc[2][8][4];
#pragma unroll
    for (int mt = 0; mt < 2; mt++)
#pragma unroll
        for (int nt = 0; nt < 8; nt++)
#pragma unroll
            for (int q = 0; q < 4; q++) acc[mt][nt][q] = 0.0f;

    // prologue: stages 0,1
    stage_load(sbase, 0, 0, tid, m0, n0);
    asm volatile("cp.async.commit_group;" ::: "memory");
    stage_load(sbase, 1, 1, tid, m0, n0);
    asm volatile("cp.async.commit_group;" ::: "memory");

#pragma unroll 1
    for (int kt = 0; kt < NKT; kt++) {
        asm volatile("cp.async.wait_group 1;" ::: "memory");
        __syncthreads();

        // issue stage kt+2 into buffer (kt+2)%3 (freed: computed at kt-1)
        if (kt + 2 < NKT)
            stage_load(sbase, (kt + 2) % 3, kt + 2, tid, m0, n0);
        asm volatile("cp.async.commit_group;" ::: "memory");

        if (kt == 32) {                  // pass boundary: acc = 2^-11 * C_res
#pragma unroll
            for (int mt = 0; mt < 2; mt++)
#pragma unroll
                for (int nt = 0; nt < 8; nt++)
#pragma unroll
                    for (int q = 0; q < 4; q++) acc[mt][nt][q] *= 4.8828125e-4f;
        }

        uint32_t stA = sbase + (uint32_t)(kt % 3) * STAGE_BYTES;
        uint32_t stB = stA + A_STG_H * 2;
#pragma unroll
        for (int ks = 0; ks < 4; ks++) {
            int kb = ks * 16;
            uint32_t a[2][4];
#pragma unroll
            for (int mt = 0; mt < 2; mt++)
                ldsm_x4(a[mt], stA + (uint32_t)((a_row + mt * 16) * ASTR + kb + a_csel) * 2);
            uint32_t bf[8][2];
#pragma unroll
            for (int p = 0; p < 4; p++) {
                uint32_t r[4];
                ldsm_x4(r, stB + (uint32_t)((wn + p * 16 + b_row) * ASTR + kb + b_csel) * 2);
                bf[2 * p][0] = r[0]; bf[2 * p][1] = r[1];
                bf[2 * p + 1][0] = r[2]; bf[2 * p + 1][1] = r[3];
            }
#pragma unroll
            for (int nt = 0; nt < 8; nt++)
#pragma unroll
                for (int mt = 0; mt < 2; mt++) {
                    float* c = acc[mt][nt];
                    asm volatile(
                        "mma.sync.aligned.m16n8k16.row.col.f32.f16.f16.f32 "
                        "{%0,%1,%2,%3}, {%4,%5,%6,%7}, {%8,%9}, {%0,%1,%2,%3};"
                        : "+f"(c[0]), "+f"(c[1]), "+f"(c[2]), "+f"(c[3])
                        : "r"(a[mt][0]), "r"(a[mt][1]), "r"(a[mt][2]), "r"(a[mt][3]),
                          "r"(bf[nt][0]), "r"(bf[nt][1]));
                }
        }
    }

    // Epilogue
#pragma unroll
    for (int mt = 0; mt < 2; mt++) {
        int row = m0 + wm + mt * 16 + lr;
#pragma unroll
        for (int nt = 0; nt < 8; nt++) {
            int col = n0 + wn + nt * 8 + lc * 2;
            float2 v0 = make_float2(acc[mt][nt][0], acc[mt][nt][1]);
            float2 v1 = make_float2(acc[mt][nt][2], acc[mt][nt][3]);
            *reinterpret_cast<float2*>(&g_weighted[(size_t)row * Hdim + col])       = v0;
            *reinterpret_cast<float2*>(&g_weighted[(size_t)(row + 8) * Hdim + col]) = v1;
        }
    }
}

// ---------------------------------------------------------------------------
// Sequential LIF scan with homeostatic threshold + 4-deep load prefetch.
// ---------------------------------------------------------------------------
__global__ __launch_bounds__(512, 2) void scan_kernel(
    const float* __restrict__ threshold,
    const float* __restrict__ p_tau_mem, const float* __restrict__ p_tau_syn,
    const float* __restrict__ p_target,  const float* __restrict__ p_lr,
    float* __restrict__ out)
{
    __shared__ float s_thr[8];
    __shared__ float s_fre[8];
    __shared__ float s_part[16][8];

    int tid     = threadIdx.x;
    int h_local = tid & 7;
    int b       = tid >> 3;
    int hblk    = blockIdx.x * 8;

    float tau_m = *p_tau_mem, tau_s = *p_tau_syn;
    float a_mem = (float)exp(-(double)(0.001f / tau_m));
    float a_syn = (float)exp(-(double)(0.001f / tau_s));
    float target = *p_target, lr = *p_lr;

    if (tid < 8) { s_thr[tid] = threshold[hblk + tid]; s_fre[tid] = 0.0f; }
    __syncthreads();

    float isyn = 0.0f, v = 0.0f;
    unsigned sb[4] = {0u, 0u, 0u, 0u};
    const float* wptr = g_weighted + (size_t)b * Hdim + hblk + h_local;
    const size_t TSTR = (size_t)Bdim * Hdim;

    float wbuf[4];
#pragma unroll
    for (int p = 0; p < 4; p++) wbuf[p] = wptr[p * TSTR];

#pragma unroll 4
    for (int t = 0; t < Tdim; ++t) {
        float w = wbuf[0];
        wbuf[0] = wbuf[1]; wbuf[1] = wbuf[2]; wbuf[2] = wbuf[3];
        if (t + 4 < Tdim) wbuf[3] = wptr[(size_t)(t + 4) * TSTR];

        isyn = fmaf(a_syn, isyn, w);
        v    = fmaf(a_mem, v, isyn);
        float thr = s_thr[h_local];
        float sp  = (v >= thr) ? 1.0f : 0.0f;
        v -= sp * thr;
        if (sp != 0.0f) sb[t >> 5] |= (1u << (t & 31));

        float r = sp;
        r += __shfl_down_sync(0xffffffffu, r, 16);
        r += __shfl_down_sync(0xffffffffu, r, 8);
        if ((tid & 31) < 8) s_part[tid >> 5][tid & 7] = r;
        __syncthreads();
        if (tid < 8) {
            float s = 0.0f;
#pragma unroll
            for (int wi = 0; wi < 16; ++wi) s += s_part[wi][tid];
            float rate = s * (1.0f / 64.0f);
            float fre  = 0.99f * s_fre[tid] + 0.01f * rate;
            s_fre[tid] = fre;
            s_thr[tid] = s_thr[tid] + lr * (fre - target);
        }
        __syncthreads();
    }

    float* p = out + ((size_t)b * Hdim + hblk + h_local) * Tdim;
#pragma unroll
    for (int wi = 0; wi < 4; ++wi) {
#pragma unroll
        for (int j = 0; j < 32; j += 4) {
            float4 o;
            o.x = (float)((sb[wi] >> (j + 0)) & 1u);
            o.y = (float)((sb[wi] >> (j + 1)) & 1u);
            o.z = (float)((sb[wi] >> (j + 2)) & 1u);
            o.w = (float)((sb[wi] >> (j + 3)) & 1u);
            *reinterpret_cast<float4*>(p + wi * 32 + j) = o;
        }
    }
}

// ---------------------------------------------------------------------------
extern "C" void kernel_launch(void* const* d_in, const int* in_sizes, int n_in,
                              void* d_out, int out_size) {
    const float* spikes    = (const float*)d_in[0];
    const float* weight    = (const float*)d_in[1];
    const float* strength  = (const float*)d_in[2];
    const float* threshold = (const float*)d_in[3];
    const float* tau_mem   = (const float*)d_in[4];
    const float* tau_syn   = (const float*)d_in[5];
    const float* target    = (const float*)d_in[6];
    const float* lr        = (const float*)d_in[7];
    float* out = (float*)d_out;

    cudaFuncSetAttribute(gemm_mma_kernel,
                         cudaFuncAttributeMaxDynamicSharedMemorySize, GEMM_SMEM);

    split_kernel<<<dim3(Idim / 32, Hdim / 32), dim3(32, 8)>>>(weight, strength);
    spike_kernel<<<dim3(Tdim / 32, Idim / 32, Bdim), dim3(32, 8)>>>(spikes);
    gemm_mma_kernel<<<dim3(Hdim / BN, Mtot / BM), 512, GEMM_SMEM>>>();
    scan_kernel<<<Hdim / 8, 512>>>(threshold, tau_mem, tau_syn, target, lr, out);
}

// round 6
// speedup vs baseline: 2.9501x; 1.0703x over previous
#include <cuda_runtime.h>
#include <cuda_fp16.h>
#include <cstdint>
#include <math.h>

#define Bdim 64
#define Idim 2048
#define Hdim 2048
#define Tdim 128
#define Mtot (Tdim * Bdim)          // 8192 rows (t,b)

// ---------------- scratch (device globals; allocation-free) ----------------
__device__ __half g_Ah[(size_t)Mtot * Idim];          // 32 MB  [t*B+b][i]
__device__ __half g_w0[(size_t)Hdim * Idim];          // 8 MB   hi plane [h][i]
__device__ __half g_w1[(size_t)Hdim * Idim];          // 8 MB   res*2^11 [h][i]
__device__ float  g_weightedT[(size_t)Tdim * Hdim * Bdim];  // 64 MB [t][h][b]

// ---------------------------------------------------------------------------
// Split + transpose: w_eff = W*S [I][H] fp32 -> 2 fp16 planes [H][I]
// ---------------------------------------------------------------------------
__global__ void split_kernel(const float* __restrict__ w, const float* __restrict__ s) {
    __shared__ float tile[32][33];
    int i0 = blockIdx.x * 32, h0 = blockIdx.y * 32;
    int tx = threadIdx.x, ty = threadIdx.y;
#pragma unroll
    for (int j = 0; j < 32; j += 8) {
        size_t idx = (size_t)(i0 + ty + j) * Hdim + h0 + tx;
        tile[ty + j][tx] = w[idx] * s[idx];
    }
    __syncthreads();
#pragma unroll
    for (int j = 0; j < 32; j += 8) {
        float v = tile[tx][ty + j];                 // [i=tx][h=ty+j]
        __half hi = __float2half_rn(v);
        float r = v - __half2float(hi);             // exact (Fast2Sum)
        __half lo = __float2half_rn(r * 2048.0f);
        size_t o = (size_t)(h0 + ty + j) * Idim + i0 + tx;
        g_w0[o] = hi;
        g_w1[o] = lo;
    }
}

// ---------------------------------------------------------------------------
// Spikes [B][I][T] fp32 -> A fp16 [(t*B+b)][i]
// ---------------------------------------------------------------------------
__global__ void spike_kernel(const float* __restrict__ in) {
    __shared__ float tile[32][33];
    int t0 = blockIdx.x * 32, i0 = blockIdx.y * 32, b = blockIdx.z;
    int tx = threadIdx.x, ty = threadIdx.y;
#pragma unroll
    for (int j = 0; j < 32; j += 8)
        tile[ty + j][tx] = in[((size_t)b * Idim + i0 + ty + j) * Tdim + t0 + tx];
    __syncthreads();
#pragma unroll
    for (int j = 0; j < 32; j += 8)
        g_Ah[((size_t)(t0 + ty + j) * Bdim + b) * Idim + i0 + tx] =
            __float2half_rn(tile[tx][ty + j]);
}

// ---------------------------------------------------------------------------
// mma.sync GEMM: C = A @ W0^T + 2^-11 * (A @ W1^T), fp32 acc.
// CTA 128x256, BK=64, 512 threads, 3-stage cp.async, ldmatrix.x4, fused
// 64-kt loop. Epilogue stages the tile through smem and writes [t][h][b].
// ---------------------------------------------------------------------------
#define BM 128
#define BN 256
#define BK 64
#define ASTR 72                          // halves per smem row (144 B)
#define A_STG_H (BM * ASTR)
#define B_STG_H (BN * ASTR)
#define STAGE_BYTES ((A_STG_H + B_STG_H) * 2)   // 55296 B
#define GEMM_SMEM (3 * STAGE_BYTES)             // 165888 B
#define NKT 64
#define EPI_STR 65                              // epilogue b-stride (floats)

__device__ __forceinline__ void ldsm_x4(uint32_t* r, uint32_t addr) {
    asm volatile("ldmatrix.sync.aligned.m8n8.x4.shared.b16 {%0,%1,%2,%3}, [%4];"
                 : "=r"(r[0]), "=r"(r[1]), "=r"(r[2]), "=r"(r[3]) : "r"(addr));
}

__device__ __forceinline__ void stage_load(uint32_t sbase, int stage, int kt,
                                           int tid, int m0, int n0) {
    const __half* Asrc = g_Ah + (size_t)m0 * Idim;
    const __half* Bsrc = (kt < 32 ? g_w1 : g_w0) + (size_t)n0 * Idim;
    int k0 = (kt & 31) * BK;
    uint32_t sA = sbase + (uint32_t)stage * STAGE_BYTES;
    uint32_t sB = sA + A_STG_H * 2;
#pragma unroll
    for (int i = 0; i < 2; i++) {
        int ch = tid + i * 512;
        int r = ch >> 3, c = ch & 7;
        uint32_t d = sA + (uint32_t)(r * ASTR + c * 8) * 2;
        asm volatile("cp.async.cg.shared.global [%0], [%1], 16;"
                     :: "r"(d), "l"(Asrc + (size_t)r * Idim + k0 + c * 8));
    }
#pragma unroll
    for (int i = 0; i < 4; i++) {
        int ch = tid + i * 512;
        int r = ch >> 3, c = ch & 7;
        uint32_t d = sB + (uint32_t)(r * ASTR + c * 8) * 2;
        asm volatile("cp.async.cg.shared.global [%0], [%1], 16;"
                     :: "r"(d), "l"(Bsrc + (size_t)r * Idim + k0 + c * 8));
    }
}

__global__ __launch_bounds__(512, 1) void gemm_mma_kernel() {
    extern __shared__ char smem[];
    uint32_t sbase = (uint32_t)__cvta_generic_to_shared(smem);

    int tid  = threadIdx.x;
    int lane = tid & 31;
    int wid  = tid >> 5;
    int wm = (wid >> 2) * 32;
    int wn = (wid & 3) * 64;
    int lr = lane >> 2;
    int lc = lane & 3;
    int m0 = blockIdx.y * BM;
    int n0 = blockIdx.x * BN;

    int a_row  = wm + (lane & 15);
    int a_csel = (lane >> 4) << 3;
    int b_row  = ((lane >> 4) << 3) + (lane & 7);
    int b_csel = ((lane >> 3) & 1) << 3;

    float acc[2][8][4];
#pragma unroll
    for (int mt = 0; mt < 2; mt++)
#pragma unroll
        for (int nt = 0; nt < 8; nt++)
#pragma unroll
            for (int q = 0; q < 4; q++) acc[mt][nt][q] = 0.0f;

    stage_load(sbase, 0, 0, tid, m0, n0);
    asm volatile("cp.async.commit_group;" ::: "memory");
    stage_load(sbase, 1, 1, tid, m0, n0);
    asm volatile("cp.async.commit_group;" ::: "memory");

#pragma unroll 1
    for (int kt = 0; kt < NKT; kt++) {
        asm volatile("cp.async.wait_group 1;" ::: "memory");
        __syncthreads();

        if (kt + 2 < NKT)
            stage_load(sbase, (kt + 2) % 3, kt + 2, tid, m0, n0);
        asm volatile("cp.async.commit_group;" ::: "memory");

        if (kt == 32) {
#pragma unroll
            for (int mt = 0; mt < 2; mt++)
#pragma unroll
                for (int nt = 0; nt < 8; nt++)
#pragma unroll
                    for (int q = 0; q < 4; q++) acc[mt][nt][q] *= 4.8828125e-4f;
        }

        uint32_t stA = sbase + (uint32_t)(kt % 3) * STAGE_BYTES;
        uint32_t stB = stA + A_STG_H * 2;
#pragma unroll
        for (int ks = 0; ks < 4; ks++) {
            int kb = ks * 16;
            uint32_t a[2][4];
#pragma unroll
            for (int mt = 0; mt < 2; mt++)
                ldsm_x4(a[mt], stA + (uint32_t)((a_row + mt * 16) * ASTR + kb + a_csel) * 2);
            uint32_t bf[8][2];
#pragma unroll
            for (int p = 0; p < 4; p++) {
                uint32_t r[4];
                ldsm_x4(r, stB + (uint32_t)((wn + p * 16 + b_row) * ASTR + kb + b_csel) * 2);
                bf[2 * p][0] = r[0]; bf[2 * p][1] = r[1];
                bf[2 * p + 1][0] = r[2]; bf[2 * p + 1][1] = r[3];
            }
#pragma unroll
            for (int nt = 0; nt < 8; nt++)
#pragma unroll
                for (int mt = 0; mt < 2; mt++) {
                    float* c = acc[mt][nt];
                    asm volatile(
                        "mma.sync.aligned.m16n8k16.row.col.f32.f16.f16.f32 "
                        "{%0,%1,%2,%3}, {%4,%5,%6,%7}, {%8,%9}, {%0,%1,%2,%3};"
                        : "+f"(c[0]), "+f"(c[1]), "+f"(c[2]), "+f"(c[3])
                        : "r"(a[mt][0]), "r"(a[mt][1]), "r"(a[mt][2]), "r"(a[mt][3]),
                          "r"(bf[nt][0]), "r"(bf[nt][1]));
                }
        }
    }

    // ---- Epilogue: stage through smem as [t_local][h][b], write coalesced ----
    __syncthreads();                       // smem free for reuse
    float* epi = reinterpret_cast<float*>(smem);   // [2][256][EPI_STR]
#pragma unroll
    for (int mt = 0; mt < 2; mt++) {
#pragma unroll
        for (int q2 = 0; q2 < 2; q2++) {           // rows r, r+8
            int row = wm + mt * 16 + lr + q2 * 8;  // local row 0..127
            int tl = row >> 6, bb = row & 63;
#pragma unroll
            for (int nt = 0; nt < 8; nt++) {
                int col = wn + nt * 8 + lc * 2;
                epi[((size_t)(tl * 256 + col)     * EPI_STR) + bb] = acc[mt][nt][q2 * 2 + 0];
                epi[((size_t)(tl * 256 + col + 1) * EPI_STR) + bb] = acc[mt][nt][q2 * 2 + 1];
            }
        }
    }
    __syncthreads();
    {
        int tl = tid >> 8;                 // 0..1
        int h  = tid & 255;                // 0..255
        int t_glob = blockIdx.y * 2 + tl;
        float* dst = g_weightedT + ((size_t)t_glob * Hdim + n0 + h) * Bdim;
        const float* src = epi + (size_t)(tl * 256 + h) * EPI_STR;
#pragma unroll
        for (int j = 0; j < 64; j += 4) {
            float4 o;
            o.x = src[j]; o.y = src[j + 1]; o.z = src[j + 2]; o.w = src[j + 3];
            *reinterpret_cast<float4*>(dst + j) = o;
        }
    }
}

// ---------------------------------------------------------------------------
// LIF scan: 8 h-groups x 64 b-threads (2 warps) per block.
// Spike count via ballot+popc (exact); thr/fre replicated in registers;
// one 64-thread named barrier per t with double-buffered partials.
// ---------------------------------------------------------------------------
__global__ __launch_bounds__(512) void scan_kernel(
    const float* __restrict__ threshold,
    const float* __restrict__ p_tau_mem, const float* __restrict__ p_tau_syn,
    const float* __restrict__ p_target,  const float* __restrict__ p_lr,
    float* __restrict__ out)
{
    __shared__ float s_part[2][8][2];

    int tid  = threadIdx.x;
    int g    = tid >> 6;                 // h-group 0..7
    int w01  = (tid >> 5) & 1;           // warp within group
    int b    = tid & 63;
    int hblk = blockIdx.x * 8;
    int h    = hblk + g;

    float tau_m = *p_tau_mem, tau_s = *p_tau_syn;
    float a_mem = (float)exp(-(double)(0.001f / tau_m));
    float a_syn = (float)exp(-(double)(0.001f / tau_s));
    float target = *p_target, lr = *p_lr;

    float thr = threshold[h];            // replicated per-thread
    float fre = 0.0f;

    float isyn = 0.0f, v = 0.0f;
    unsigned sb[4] = {0u, 0u, 0u, 0u};
    const float* wptr = g_weightedT + (size_t)h * Bdim + b;
    const size_t TSTR = (size_t)Hdim * Bdim;

    float wbuf[4];
#pragma unroll
    for (int p = 0; p < 4; p++) wbuf[p] = wptr[p * TSTR];

#pragma unroll 4
    for (int t = 0; t < Tdim; ++t) {
        float w = wbuf[0];
        wbuf[0] = wbuf[1]; wbuf[1] = wbuf[2]; wbuf[2] = wbuf[3];
        if (t + 4 < Tdim) wbuf[3] = wptr[(size_t)(t + 4) * TSTR];

        isyn = fmaf(a_syn, isyn, w);
        v    = fmaf(a_mem, v, isyn);
        bool pred = (v >= thr);
        if (pred) { v -= thr; sb[t >> 5] |= (1u << (t & 31)); }

        unsigned mask = __ballot_sync(0xffffffffu, pred);
        if ((tid & 31) == 0)
            s_part[t & 1][g][w01] = (float)__popc(mask);
        asm volatile("bar.sync %0, 64;" :: "r"(g + 1) : "memory");
        float s = s_part[t & 1][g][0] + s_part[t & 1][g][1];   // exact int sum

        float rate = s * (1.0f / 64.0f);
        fre = 0.99f * fre + 0.01f * rate;
        thr = thr + lr * (fre - target);
    }

    float* p = out + ((size_t)b * Hdim + h) * Tdim;
#pragma unroll
    for (int wi = 0; wi < 4; ++wi) {
#pragma unroll
        for (int j = 0; j < 32; j += 4) {
            float4 o;
            o.x = (float)((sb[wi] >> (j + 0)) & 1u);
            o.y = (float)((sb[wi] >> (j + 1)) & 1u);
            o.z = (float)((sb[wi] >> (j + 2)) & 1u);
            o.w = (float)((sb[wi] >> (j + 3)) & 1u);
            *reinterpret_cast<float4*>(p + wi * 32 + j) = o;
        }
    }
}

// ---------------------------------------------------------------------------
extern "C" void kernel_launch(void* const* d_in, const int* in_sizes, int n_in,
                              void* d_out, int out_size) {
    const float* spikes    = (const float*)d_in[0];
    const float* weight    = (const float*)d_in[1];
    const float* strength  = (const float*)d_in[2];
    const float* threshold = (const float*)d_in[3];
    const float* tau_mem   = (const float*)d_in[4];
    const float* tau_syn   = (const float*)d_in[5];
    const float* target    = (const float*)d_in[6];
    const float* lr        = (const float*)d_in[7];
    float* out = (float*)d_out;

    cudaFuncSetAttribute(gemm_mma_kernel,
                         cudaFuncAttributeMaxDynamicSharedMemorySize, GEMM_SMEM);

    split_kernel<<<dim3(Idim / 32, Hdim / 32), dim3(32, 8)>>>(weight, strength);
    spike_kernel<<<dim3(Tdim / 32, Idim / 32, Bdim), dim3(32, 8)>>>(spikes);
    gemm_mma_kernel<<<dim3(Hdim / BN, Mtot / BM), 512, GEMM_SMEM>>>();
    scan_kernel<<<Hdim / 8, 512>>>(threshold, tau_mem, tau_syn, target, lr, out);
}

// round 8
// speedup vs baseline: 3.0280x; 1.0264x over previous
#include <cuda_runtime.h>
#include <cuda_fp16.h>
#include <cstdint>
#include <math.h>

#define Bdim 64
#define Idim 2048
#define Hdim 2048
#define Tdim 128
#define Mtot (Tdim * Bdim)          // 8192 rows (t,b)

// ---------------- scratch (device globals; allocation-free) ----------------
__device__ __half g_Ah[(size_t)Mtot * Idim];          // 32 MB  [t*B+b][i]
__device__ __half g_w0[(size_t)Hdim * Idim];          // 8 MB   hi plane [h][i]
__device__ __half g_w1[(size_t)Hdim * Idim];          // 8 MB   res*2^11 [h][i]
__device__ float  g_weightedT[(size_t)Tdim * Hdim * Bdim];  // 64 MB [t][h][b]

// ---------------------------------------------------------------------------
// Fused prep: blocks [0,16384): spike transpose+convert; [16384,20480): split.
// ---------------------------------------------------------------------------
__global__ void prep_kernel(const float* __restrict__ in,
                            const float* __restrict__ w,
                            const float* __restrict__ s) {
    __shared__ float tile[32][33];
    int bid = blockIdx.x;
    int tx = threadIdx.x, ty = threadIdx.y;

    if (bid < 16384) {
        // spikes [B][I][T] fp32 -> g_Ah [(t*B+b)][i] fp16
        int t0 = (bid & 3) * 32;
        int i0 = ((bid >> 2) & 63) * 32;
        int b  = bid >> 8;
#pragma unroll
        for (int j = 0; j < 32; j += 8)
            tile[ty + j][tx] = in[((size_t)b * Idim + i0 + ty + j) * Tdim + t0 + tx];
        __syncthreads();
#pragma unroll
        for (int j = 0; j < 32; j += 8)
            g_Ah[((size_t)(t0 + ty + j) * Bdim + b) * Idim + i0 + tx] =
                __float2half_rn(tile[tx][ty + j]);
    } else {
        // w_eff = W*S [I][H] fp32 -> 2 fp16 planes [H][I]
        int sid = bid - 16384;
        int i0 = (sid & 63) * 32;
        int h0 = (sid >> 6) * 32;
#pragma unroll
        for (int j = 0; j < 32; j += 8) {
            size_t idx = (size_t)(i0 + ty + j) * Hdim + h0 + tx;
            tile[ty + j][tx] = w[idx] * s[idx];
        }
        __syncthreads();
#pragma unroll
        for (int j = 0; j < 32; j += 8) {
            float v = tile[tx][ty + j];                 // [i=tx][h=ty+j]
            __half hi = __float2half_rn(v);
            float r = v - __half2float(hi);             // exact (Fast2Sum)
            __half lo = __float2half_rn(r * 2048.0f);
            size_t o = (size_t)(h0 + ty + j) * Idim + i0 + tx;
            g_w0[o] = hi;
            g_w1[o] = lo;
        }
    }
}

// ---------------------------------------------------------------------------
// mma.sync GEMM: C = A @ W0^T + 2^-11 * (A @ W1^T), fp32 acc.  (R6 verbatim)
// CTA 128x256, BK=64, 512 threads, 3-stage cp.async, ldmatrix.x4, fused
// 64-kt loop. Epilogue stages the tile through smem and writes [t][h][b].
// ---------------------------------------------------------------------------
#define BM 128
#define BN 256
#define BK 64
#define ASTR 72                          // halves per smem row (144 B)
#define A_STG_H (BM * ASTR)
#define B_STG_H (BN * ASTR)
#define STAGE_BYTES ((A_STG_H + B_STG_H) * 2)   // 55296 B
#define GEMM_SMEM (3 * STAGE_BYTES)             // 165888 B
#define NKT 64
#define EPI_STR 65

__device__ __forceinline__ void ldsm_x4(uint32_t* r, uint32_t addr) {
    asm volatile("ldmatrix.sync.aligned.m8n8.x4.shared.b16 {%0,%1,%2,%3}, [%4];"
                 : "=r"(r[0]), "=r"(r[1]), "=r"(r[2]), "=r"(r[3]) : "r"(addr));
}

__device__ __forceinline__ void stage_load(uint32_t sbase, int stage, int kt,
                                           int tid, int m0, int n0) {
    const __half* Asrc = g_Ah + (size_t)m0 * Idim;
    const __half* Bsrc = (kt < 32 ? g_w1 : g_w0) + (size_t)n0 * Idim;
    int k0 = (kt & 31) * BK;
    uint32_t sA = sbase + (uint32_t)stage * STAGE_BYTES;
    uint32_t sB = sA + A_STG_H * 2;
#pragma unroll
    for (int i = 0; i < 2; i++) {
        int ch = tid + i * 512;
        int r = ch >> 3, c = ch & 7;
        uint32_t d = sA + (uint32_t)(r * ASTR + c * 8) * 2;
        asm volatile("cp.async.cg.shared.global [%0], [%1], 16;"
                     :: "r"(d), "l"(Asrc + (size_t)r * Idim + k0 + c * 8));
    }
#pragma unroll
    for (int i = 0; i < 4; i++) {
        int ch = tid + i * 512;
        int r = ch >> 3, c = ch & 7;
        uint32_t d = sB + (uint32_t)(r * ASTR + c * 8) * 2;
        asm volatile("cp.async.cg.shared.global [%0], [%1], 16;"
                     :: "r"(d), "l"(Bsrc + (size_t)r * Idim + k0 + c * 8));
    }
}

__global__ __launch_bounds__(512, 1) void gemm_mma_kernel() {
    extern __shared__ char smem[];
    uint32_t sbase = (uint32_t)__cvta_generic_to_shared(smem);

    int tid  = threadIdx.x;
    int lane = tid & 31;
    int wid  = tid >> 5;
    int wm = (wid >> 2) * 32;
    int wn = (wid & 3) * 64;
    int lr = lane >> 2;
    int lc = lane & 3;
    int m0 = blockIdx.y * BM;
    int n0 = blockIdx.x * BN;

    int a_row  = wm + (lane & 15);
    int a_csel = (lane >> 4) << 3;
    int b_row  = ((lane >> 4) << 3) + (lane & 7);
    int b_csel = ((lane >> 3) & 1) << 3;

    float acc[2][8][4];
#pragma unroll
    for (int mt = 0; mt < 2; mt++)
#pragma unroll
        for (int nt = 0; nt < 8; nt++)
#pragma unroll
            for (int q = 0; q < 4; q++) acc[mt][nt][q] = 0.0f;

    stage_load(sbase, 0, 0, tid, m0, n0);
    asm volatile("cp.async.commit_group;" ::: "memory");
    stage_load(sbase, 1, 1, tid, m0, n0);
    asm volatile("cp.async.commit_group;" ::: "memory");

#pragma unroll 1
    for (int kt = 0; kt < NKT; kt++) {
        asm volatile("cp.async.wait_group 1;" ::: "memory");
        __syncthreads();

        if (kt + 2 < NKT)
            stage_load(sbase, (kt + 2) % 3, kt + 2, tid, m0, n0);
        asm volatile("cp.async.commit_group;" ::: "memory");

        if (kt == 32) {
#pragma unroll
            for (int mt = 0; mt < 2; mt++)
#pragma unroll
                for (int nt = 0; nt < 8; nt++)
#pragma unroll
                    for (int q = 0; q < 4; q++) acc[mt][nt][q] *= 4.8828125e-4f;
        }

        uint32_t stA = sbase + (uint32_t)(kt % 3) * STAGE_BYTES;
        uint32_t stB = stA + A_STG_H * 2;
#pragma unroll
        for (int ks = 0; ks < 4; ks++) {
            int kb = ks * 16;
            uint32_t a[2][4];
#pragma unroll
            for (int mt = 0; mt < 2; mt++)
                ldsm_x4(a[mt], stA + (uint32_t)((a_row + mt * 16) * ASTR + kb + a_csel) * 2);
            uint32_t bf[8][2];
#pragma unroll
            for (int p = 0; p < 4; p++) {
                uint32_t r[4];
                ldsm_x4(r, stB + (uint32_t)((wn + p * 16 + b_row) * ASTR + kb + b_csel) * 2);
                bf[2 * p][0] = r[0]; bf[2 * p][1] = r[1];
                bf[2 * p + 1][0] = r[2]; bf[2 * p + 1][1] = r[3];
            }
#pragma unroll
            for (int nt = 0; nt < 8; nt++)
#pragma unroll
                for (int mt = 0; mt < 2; mt++) {
                    float* c = acc[mt][nt];
                    asm volatile(
                        "mma.sync.aligned.m16n8k16.row.col.f32.f16.f16.f32 "
                        "{%0,%1,%2,%3}, {%4,%5,%6,%7}, {%8,%9}, {%0,%1,%2,%3};"
                        : "+f"(c[0]), "+f"(c[1]), "+f"(c[2]), "+f"(c[3])
                        : "r"(a[mt][0]), "r"(a[mt][1]), "r"(a[mt][2]), "r"(a[mt][3]),
                          "r"(bf[nt][0]), "r"(bf[nt][1]));
                }
        }
    }

    // ---- Epilogue: stage through smem as [t_local][h][b], write coalesced ----
    __syncthreads();
    float* epi = reinterpret_cast<float*>(smem);   // [2][256][EPI_STR]
#pragma unroll
    for (int mt = 0; mt < 2; mt++) {
#pragma unroll
        for (int q2 = 0; q2 < 2; q2++) {
            int row = wm + mt * 16 + lr + q2 * 8;   // local row 0..127
            int tl = row >> 6, bb = row & 63;
#pragma unroll
            for (int nt = 0; nt < 8; nt++) {
                int col = wn + nt * 8 + lc * 2;
                epi[((size_t)(tl * 256 + col)     * EPI_STR) + bb] = acc[mt][nt][q2 * 2 + 0];
                epi[((size_t)(tl * 256 + col + 1) * EPI_STR) + bb] = acc[mt][nt][q2 * 2 + 1];
            }
        }
    }
    __syncthreads();
    {
        int tl = tid >> 8;
        int h  = tid & 255;
        int t_glob = blockIdx.y * 2 + tl;
        float* dst = g_weightedT + ((size_t)t_glob * Hdim + n0 + h) * Bdim;
        const float* src = epi + (size_t)(tl * 256 + h) * EPI_STR;
#pragma unroll
        for (int j = 0; j < 64; j += 4) {
            float4 o;
            o.x = src[j]; o.y = src[j + 1]; o.z = src[j + 2]; o.w = src[j + 3];
            *reinterpret_cast<float4*>(dst + j) = o;
        }
    }
}

// ---------------------------------------------------------------------------
// LIF scan: one warp per h, each lane owns b = 2*lane, 2*lane+1.
// Spike count via ballot+popc (exact) — no smem, no barriers.
// Output via in-warp shfl redistribution -> fully coalesced 512B runs.
// ---------------------------------------------------------------------------
__global__ __launch_bounds__(256) void scan_kernel(
    const float* __restrict__ threshold,
    const float* __restrict__ p_tau_mem, const float* __restrict__ p_tau_syn,
    const float* __restrict__ p_target,  const float* __restrict__ p_lr,
    float* __restrict__ out)
{
    int tid  = threadIdx.x;
    int lane = tid & 31;
    int h    = blockIdx.x * 8 + (tid >> 5);

    float tau_m = *p_tau_mem, tau_s = *p_tau_syn;
    float a_mem = (float)exp(-(double)(0.001f / tau_m));
    float a_syn = (float)exp(-(double)(0.001f / tau_s));
    float target = *p_target, lr = *p_lr;

    float thr = threshold[h];
    float fre = 0.0f;
    float isyn0 = 0.0f, v0 = 0.0f, isyn1 = 0.0f, v1 = 0.0f;
    unsigned sb0[4] = {0u, 0u, 0u, 0u};
    unsigned sb1[4] = {0u, 0u, 0u, 0u};

    const float* wptr = g_weightedT + (size_t)h * Bdim + lane * 2;
    const size_t TSTR = (size_t)Hdim * Bdim;

    float2 wbuf[4];
#pragma unroll
    for (int p = 0; p < 4; p++)
        wbuf[p] = *reinterpret_cast<const float2*>(wptr + p * TSTR);

#pragma unroll 4
    for (int t = 0; t < Tdim; ++t) {
        float2 w = wbuf[0];
        wbuf[0] = wbuf[1]; wbuf[1] = wbuf[2]; wbuf[2] = wbuf[3];
        if (t + 4 < Tdim)
            wbuf[3] = *reinterpret_cast<const float2*>(wptr + (size_t)(t + 4) * TSTR);

        isyn0 = fmaf(a_syn, isyn0, w.x);
        v0    = fmaf(a_mem, v0, isyn0);
        isyn1 = fmaf(a_syn, isyn1, w.y);
        v1    = fmaf(a_mem, v1, isyn1);
        bool p0 = (v0 >= thr), p1 = (v1 >= thr);
        if (p0) { v0 -= thr; sb0[t >> 5] |= (1u << (t & 31)); }
        if (p1) { v1 -= thr; sb1[t >> 5] |= (1u << (t & 31)); }

        unsigned m0 = __ballot_sync(0xffffffffu, p0);
        unsigned m1 = __ballot_sync(0xffffffffu, p1);
        float s = (float)(__popc(m0) + __popc(m1));      // exact int

        float rate = s * (1.0f / 64.0f);
        fre = 0.99f * fre + 0.01f * rate;
        thr = thr + lr * (fre - target);
    }

    // ---- Output: out[b][h][t]; warp cooperatively writes each b-row ----
    int bsel = (lane & 7) * 4;              // bit base within word
#pragma unroll 4
    for (int bb = 0; bb < 64; ++bb) {
        int src = bb >> 1;
        unsigned w0, w1, w2, w3;
        if (bb & 1) {
            w0 = __shfl_sync(0xffffffffu, sb1[0], src);
            w1 = __shfl_sync(0xffffffffu, sb1[1], src);
            w2 = __shfl_sync(0xffffffffu, sb1[2], src);
            w3 = __shfl_sync(0xffffffffu, sb1[3], src);
        } else {
            w0 = __shfl_sync(0xffffffffu, sb0[0], src);
            w1 = __shfl_sync(0xffffffffu, sb0[1], src);
            w2 = __shfl_sync(0xffffffffu, sb0[2], src);
            w3 = __shfl_sync(0xffffffffu, sb0[3], src);
        }
        unsigned wsel = (lane < 8) ? w0 : (lane < 16) ? w1 : (lane < 24) ? w2 : w3;
        unsigned bits = (wsel >> bsel) & 0xFu;
        float4 o;
        o.x = (float)(bits & 1u);
        o.y = (float)((bits >> 1) & 1u);
        o.z = (float)((bits >> 2) & 1u);
        o.w = (float)((bits >> 3) & 1u);
        *reinterpret_cast<float4*>(
            out + ((size_t)bb * Hdim + h) * Tdim + lane * 4) = o;
    }
}

// ---------------------------------------------------------------------------
extern "C" void kernel_launch(void* const* d_in, const int* in_sizes, int n_in,
                              void* d_out, int out_size) {
    const float* spikes    = (const float*)d_in[0];
    const float* weight    = (const float*)d_in[1];
    const float* strength  = (const float*)d_in[2];
    const float* threshold = (const float*)d_in[3];
    const float* tau_mem   = (const float*)d_in[4];
    const float* tau_syn   = (const float*)d_in[5];
    const float* target    = (const float*)d_in[6];
    const float* lr        = (const float*)d_in[7];
    float* out = (float*)d_out;

    cudaFuncSetAttribute(gemm_mma_kernel,
                         cudaFuncAttributeMaxDynamicSharedMemorySize, GEMM_SMEM);

    prep_kernel<<<20480, dim3(32, 8)>>>(spikes, weight, strength);
    gemm_mma_kernel<<<dim3(Hdim / BN, Mtot / BM), 512, GEMM_SMEM>>>();
    scan_kernel<<<Hdim / 8, 256>>>(threshold, tau_mem, tau_syn, target, lr, out);
}